// round 11
// baseline (speedup 1.0000x reference)
#include <cuda_runtime.h>

// DWT Haar loss: pred/target [32,3,512,512] fp32.
// Linear DWT -> operate on diff. Per 2x2 block (a,b,c,d) of diff:
//   contribution = |a+b+c+d| + |a+b-c-d| + |a-b+c-d| + |a-b-c+d|
// loss = 0.5 * sum / N_blocks.
//
// Viewed as 24576 row-pairs of 512 floats (128 float4 per row).
// Work item = one float4 from row 2m + matching float4 from row 2m+1 (both
// tensors) = two 2x2 blocks. Simple grid-stride loop (fastest raw body
// across R1-R7), single resident wave (148 SMs x 8 CTAs), streaming loads
// (__ldcs: read-once data, evict-first L2). Last CTA finalizes the scalar
// (release/acquire protocol) and resets state for the next graph replay.

static constexpr int TOTAL_QUADS = 24576 * 128;       // 3,145,728
static constexpr float SCALE = 0.5f / 6291456.0f;     // 0.5 / N_blocks
static constexpr int GRID = 148 * 8;                  // single wave
static constexpr int BLOCK = 256;

__device__ float    g_scratch = 0.0f;
__device__ unsigned g_ctr     = 0u;

__device__ __forceinline__ void fence_acq_rel_gpu() {
    asm volatile("fence.acq_rel.gpu;" ::: "memory");
}

__global__ void __launch_bounds__(BLOCK) dwt_loss_kernel(
    const float4* __restrict__ pred,
    const float4* __restrict__ tgt,
    float* __restrict__ out)
{
    float acc = 0.0f;
    const int stride = GRID * BLOCK;
    for (int i = blockIdx.x * BLOCK + threadIdx.x; i < TOTAL_QUADS; i += stride) {
        const int m = i >> 7;            // row-pair index
        const int q = i & 127;           // float4 index within row
        const int base0 = m * 256 + q;   // row 2m   (float4 units)
        const int base1 = base0 + 128;   // row 2m+1

        float4 p0 = __ldcs(&pred[base0]);
        float4 p1 = __ldcs(&pred[base1]);
        float4 t0 = __ldcs(&tgt[base0]);
        float4 t1 = __ldcs(&tgt[base1]);

        // Block 0: cols 4q, 4q+1
        {
            float a = p0.x - t0.x, b = p0.y - t0.y;
            float c = p1.x - t1.x, d = p1.y - t1.y;
            float apb = a + b, amb = a - b, cpd = c + d, cmd = c - d;
            acc += fabsf(apb + cpd) + fabsf(apb - cpd)
                 + fabsf(amb + cmd) + fabsf(amb - cmd);
        }
        // Block 1: cols 4q+2, 4q+3
        {
            float a = p0.z - t0.z, b = p0.w - t0.w;
            float c = p1.z - t1.z, d = p1.w - t1.w;
            float apb = a + b, amb = a - b, cpd = c + d, cmd = c - d;
            acc += fabsf(apb + cpd) + fabsf(apb - cpd)
                 + fabsf(amb + cmd) + fabsf(amb - cmd);
        }
    }

    // Warp reduction
    #pragma unroll
    for (int o = 16; o > 0; o >>= 1)
        acc += __shfl_xor_sync(0xffffffffu, acc, o);

    __shared__ float warp_sums[8];
    if ((threadIdx.x & 31) == 0)
        warp_sums[threadIdx.x >> 5] = acc;
    __syncthreads();

    if (threadIdx.x < 32) {
        float v = (threadIdx.x < 8) ? warp_sums[threadIdx.x] : 0.0f;
        #pragma unroll
        for (int o = 4; o > 0; o >>= 1)
            v += __shfl_xor_sync(0xffffffffu, v, o);

        if (threadIdx.x == 0) {
            atomicAdd(&g_scratch, v);          // RED to L2 (no return)
            fence_acq_rel_gpu();               // release scratch before ctr
            unsigned old = atomicAdd(&g_ctr, 1u);
            if (old == GRID - 1) {
                fence_acq_rel_gpu();           // acquire: see all scratch adds
                float total = atomicAdd(&g_scratch, 0.0f);
                out[0] = total * SCALE;
                atomicExch(&g_scratch, 0.0f);  // reset for next graph replay
                atomicExch(&g_ctr, 0u);
            }
        }
    }
}

extern "C" void kernel_launch(void* const* d_in, const int* in_sizes, int n_in,
                              void* d_out, int out_size) {
    const float4* pred = (const float4*)d_in[0];
    const float4* tgt  = (const float4*)d_in[1];
    float* out = (float*)d_out;

    dwt_loss_kernel<<<GRID, BLOCK>>>(pred, tgt, out);
}

// round 16
// speedup vs baseline: 1.0395x; 1.0395x over previous
#include <cuda_runtime.h>

// DWT Haar loss: pred/target [32,3,512,512] fp32.
// Linear DWT -> operate on diff. Per 2x2 block (a,b,c,d) of diff:
//   contribution = |a+b+c+d| + |a+b-c-d| + |a-b+c-d| + |a-b-c+d|
// loss = 0.5 * sum / N_blocks.
//
// Viewed as 24576 row-pairs of 512 floats (128 float4 per row).
// Work item = one float4 from row 2m + matching float4 from row 2m+1 (both
// tensors) = two 2x2 blocks. Simple grid-stride loop, grid 2368 (2 waves;
// single-wave R11 exposed CTA-spread as tail idle, occ 91->66%). Loads use
// ld.global.nc with L2::256B prefetch hint (one-pass streaming read).
// Single kernel: last CTA finalizes scalar (release/acquire) and resets
// state for the next graph replay (no memset node: saves ~2us end-to-end).

static constexpr int TOTAL_QUADS = 24576 * 128;       // 3,145,728
static constexpr float SCALE = 0.5f / 6291456.0f;     // 0.5 / N_blocks
static constexpr int GRID = 2368;
static constexpr int BLOCK = 256;

__device__ float    g_scratch = 0.0f;
__device__ unsigned g_ctr     = 0u;

__device__ __forceinline__ void fence_acq_rel_gpu() {
    asm volatile("fence.acq_rel.gpu;" ::: "memory");
}

__device__ __forceinline__ float4 ldg_pf256(const float4* p) {
    float4 v;
    asm("ld.global.nc.L2::256B.v4.f32 {%0,%1,%2,%3}, [%4];"
        : "=f"(v.x), "=f"(v.y), "=f"(v.z), "=f"(v.w)
        : "l"(p));
    return v;
}

__global__ void __launch_bounds__(BLOCK) dwt_loss_kernel(
    const float4* __restrict__ pred,
    const float4* __restrict__ tgt,
    float* __restrict__ out)
{
    float acc = 0.0f;
    const int stride = GRID * BLOCK;
    for (int i = blockIdx.x * BLOCK + threadIdx.x; i < TOTAL_QUADS; i += stride) {
        const int m = i >> 7;            // row-pair index
        const int q = i & 127;           // float4 index within row
        const int base0 = m * 256 + q;   // row 2m   (float4 units)
        const int base1 = base0 + 128;   // row 2m+1

        float4 p0 = ldg_pf256(&pred[base0]);
        float4 p1 = ldg_pf256(&pred[base1]);
        float4 t0 = ldg_pf256(&tgt[base0]);
        float4 t1 = ldg_pf256(&tgt[base1]);

        // Block 0: cols 4q, 4q+1
        {
            float a = p0.x - t0.x, b = p0.y - t0.y;
            float c = p1.x - t1.x, d = p1.y - t1.y;
            float apb = a + b, amb = a - b, cpd = c + d, cmd = c - d;
            acc += fabsf(apb + cpd) + fabsf(apb - cpd)
                 + fabsf(amb + cmd) + fabsf(amb - cmd);
        }
        // Block 1: cols 4q+2, 4q+3
        {
            float a = p0.z - t0.z, b = p0.w - t0.w;
            float c = p1.z - t1.z, d = p1.w - t1.w;
            float apb = a + b, amb = a - b, cpd = c + d, cmd = c - d;
            acc += fabsf(apb + cpd) + fabsf(apb - cpd)
                 + fabsf(amb + cmd) + fabsf(amb - cmd);
        }
    }

    // Warp reduction
    #pragma unroll
    for (int o = 16; o > 0; o >>= 1)
        acc += __shfl_xor_sync(0xffffffffu, acc, o);

    __shared__ float warp_sums[8];
    if ((threadIdx.x & 31) == 0)
        warp_sums[threadIdx.x >> 5] = acc;
    __syncthreads();

    if (threadIdx.x < 32) {
        float v = (threadIdx.x < 8) ? warp_sums[threadIdx.x] : 0.0f;
        #pragma unroll
        for (int o = 4; o > 0; o >>= 1)
            v += __shfl_xor_sync(0xffffffffu, v, o);

        if (threadIdx.x == 0) {
            atomicAdd(&g_scratch, v);          // RED to L2 (no return)
            fence_acq_rel_gpu();               // release scratch before ctr
            unsigned old = atomicAdd(&g_ctr, 1u);
            if (old == GRID - 1) {
                fence_acq_rel_gpu();           // acquire: see all scratch adds
                float total = atomicAdd(&g_scratch, 0.0f);
                out[0] = total * SCALE;
                atomicExch(&g_scratch, 0.0f);  // reset for next graph replay
                atomicExch(&g_ctr, 0u);
            }
        }
    }
}

extern "C" void kernel_launch(void* const* d_in, const int* in_sizes, int n_in,
                              void* d_out, int out_size) {
    const float4* pred = (const float4*)d_in[0];
    const float4* tgt  = (const float4*)d_in[1];
    float* out = (float*)d_out;

    dwt_loss_kernel<<<GRID, BLOCK>>>(pred, tgt, out);
}